// round 16
// baseline (speedup 1.0000x reference)
#include <cuda_runtime.h>

// ---------------------------------------------------------------------------
// Fused FourierLayer MoE, fixed shapes:
//   B=2, T=32, C=1, H=16, W=16, D=128, E=9, TOP_K=2  ->  N = 512 tokens
// R16 = R14 with the __ldg overload fixed (load via uint4, bit-cast to u64
// pair). Prep kernel pre-duplicates weights as {v,v} u64 pairs so GEMM loops
// are LDG.128 -> FFMA2 with no dup MOVs (alu pipe freed, dep chain shortened).
// ---------------------------------------------------------------------------

typedef unsigned long long u64;
typedef unsigned int u32;
struct ull2 { u64 x, y; };

#define TT 32
#define DD 128
#define EE 9
#define NTOK 512
#define PCH 36   // float pitch: 144B rows -> 16B-aligned, conflict-free LDS.128

#define FFMA2(d, a, b, c) \
    asm("fma.rn.f32x2 %0, %1, %2, %3;" : "=l"(d) : "l"(a), "l"(b), "l"(c))

__device__ __forceinline__ u64 dup_f32(float v) {
    u32 u = __float_as_uint(v);
    u64 r;
    asm("mov.b64 %0, {%1, %1};" : "=l"(r) : "r"(u));
    return r;
}
__device__ __forceinline__ void unpack_f32x2(u64 p, float &lo, float &hi) {
    u32 a, b;
    asm("mov.b64 {%0, %1}, %2;" : "=r"(a), "=r"(b) : "l"(p));
    lo = __uint_as_float(a); hi = __uint_as_float(b);
}

// __ldg a 16B pre-duplicated weight chunk; uint4 lanes alias into u64 halves.
__device__ __forceinline__ ull2 ldg_w(const ull2* p) {
    uint4 v = __ldg((const uint4*)p);
    ull2 r;
    asm("mov.b64 %0, {%2, %3}; mov.b64 %1, {%4, %5};"
        : "=l"(r.x), "=l"(r.y)
        : "r"(v.x), "r"(v.y), "r"(v.z), "r"(v.w));
    return r;
}

// e^x for x <= 0, FMA-pipe only. |rel err| < ~2e-7.
__device__ __forceinline__ float exp_neg_fast(float x) {
    float z = x * 1.4426950408889634f;
    z = fmaxf(z, -126.0f);
    float fn = rintf(z);
    float f  = z - fn;
    float p  = 1.5403506e-4f;
    p = fmaf(p, f, 1.3333558e-3f);
    p = fmaf(p, f, 9.6181291e-3f);
    p = fmaf(p, f, 5.5504109e-2f);
    p = fmaf(p, f, 2.4022651e-1f);
    p = fmaf(p, f, 6.9314718e-1f);
    p = fmaf(p, f, 1.0f);
    return p * __int_as_float(((int)fn + 127) << 23);
}

template<int FB>
__device__ __forceinline__ float dft_amp(const float* __restrict__ xr) {
    static constexpr float COS32[32] = {
         1.0f,           0.98078528040f,  0.92387953251f,  0.83146961230f,
         0.70710678119f, 0.55557023302f,  0.38268343237f,  0.19509032202f,
         0.0f,          -0.19509032202f, -0.38268343237f, -0.55557023302f,
        -0.70710678119f,-0.83146961230f, -0.92387953251f, -0.98078528040f,
        -1.0f,          -0.98078528040f, -0.92387953251f, -0.83146961230f,
        -0.70710678119f,-0.55557023302f, -0.38268343237f, -0.19509032202f,
         0.0f,           0.19509032202f,  0.38268343237f,  0.55557023302f,
         0.70710678119f, 0.83146961230f,  0.92387953251f,  0.98078528040f };
    float re = 0.0f, im = 0.0f;
#pragma unroll
    for (int t = 0; t < 32; t++) {
        const float c = COS32[(FB * t) & 31];
        const float s = COS32[((FB * t) + 24) & 31];
        if (c != 0.0f) re = fmaf(xr[t], c, re);
        if (s != 0.0f) im = fmaf(xr[t], s, im);
    }
    return sqrtf(fmaf(re, re, im * im)) * 0.17677669529663688f;
}

// ---- pre-duplicated weight scratch ----------------------------------------
// gWf[d*64 + cp]    = { dup(w_fuse[d][2cp]), dup(w_fuse[d][2cp+1]) }
// gWe[e][d*64 + cp] = { dup(We[e][d][2cp]),  dup(We[e][d][2cp+1])  }
__device__ ull2 gWf[DD * 64];
__device__ ull2 gWe[EE * DD * 64];

__global__ void prep_dup(const float* __restrict__ w_fuse,
                         const float* __restrict__ We) {
    int idx = blockIdx.x * 256 + threadIdx.x;   // 0 .. (1+EE)*8192-1
    int total = (1 + EE) * DD * 64;
    if (idx >= total) return;
    ull2 o;
    if (idx < DD * 64) {
        float2 v = *(const float2*)(w_fuse + idx * 2);
        o.x = dup_f32(v.x); o.y = dup_f32(v.y);
        gWf[idx] = o;
    } else {
        int r = idx - DD * 64;
        float2 v = *(const float2*)(We + (size_t)r * 2);
        o.x = dup_f32(v.x); o.y = dup_f32(v.y);
        gWe[r] = o;
    }
}

__global__ __launch_bounds__(128, 4)
void moe_fused_kernel(const float* __restrict__ x,
                      const float* __restrict__ b_fuse,
                      const float* __restrict__ w_gate,
                      const float* __restrict__ be,
                      float* __restrict__ out)
{
    __shared__ __align__(16) float shBuf[8192];
    __shared__ float wgS[16 * EE];
    __shared__ float shRed[4 * EE];
    __shared__ int   shE[2];
    __shared__ float shG[2];

    float* xS = shBuf;

    const int n    = blockIdx.x;
    const int tid  = threadIdx.x;
    const int b    = n >> 8;
    const int hw   = n & 255;
    const int lane = tid & 31;
    const int w1   = tid >> 5;

    // ---- stage 0: tables + x tile load (transpose into xS[d][t]) ----------
    for (int i = tid; i < 16 * EE; i += 128) wgS[i] = w_gate[i];

    {
        const float2* x2 = (const float2*)(x + (((size_t)b * TT) << 15) + ((size_t)hw << 7));
#pragma unroll
        for (int k = 0; k < 16; k++) {
            int idx = k * 128 + tid;
            int t   = idx >> 6;
            int d2  = idx & 63;
            float2 v = __ldg(x2 + (size_t)t * 16384 + d2);
            xS[(2 * d2)     * PCH + t] = v.x;
            xS[(2 * d2 + 1) * PCH + t] = v.y;
        }
    }
    __syncthreads();

    // ---- stage 1: fuse GEMM  (thread: 2 cols x 16 t) -----------------------
    const int cw1 = w1 & 1;
    const int tg1 = w1 >> 1;           // 0..1
    const int cp0 = cw1 * 32 + lane;   // col-pair index (cols 2cp0, 2cp0+1)
    const int c0  = 2 * cp0;

    u64 acc1[8][2];
    {
        u64 bd0 = dup_f32(__ldg(b_fuse + c0));
        u64 bd1 = dup_f32(__ldg(b_fuse + c0 + 1));
#pragma unroll
        for (int j = 0; j < 8; j++) { acc1[j][0] = bd0; acc1[j][1] = bd1; }
#pragma unroll 8
        for (int d = 0; d < DD; d++) {
            const float* ar = &xS[d * PCH + tg1 * 16];
            ull2 A0 = *(const ull2*)ar;
            ull2 A1 = *(const ull2*)(ar + 4);
            ull2 A2 = *(const ull2*)(ar + 8);
            ull2 A3 = *(const ull2*)(ar + 12);
            ull2 wd = ldg_w(gWf + d * 64 + cp0);
            FFMA2(acc1[0][0], A0.x, wd.x, acc1[0][0]);
            FFMA2(acc1[0][1], A0.x, wd.y, acc1[0][1]);
            FFMA2(acc1[1][0], A0.y, wd.x, acc1[1][0]);
            FFMA2(acc1[1][1], A0.y, wd.y, acc1[1][1]);
            FFMA2(acc1[2][0], A1.x, wd.x, acc1[2][0]);
            FFMA2(acc1[2][1], A1.x, wd.y, acc1[2][1]);
            FFMA2(acc1[3][0], A1.y, wd.x, acc1[3][0]);
            FFMA2(acc1[3][1], A1.y, wd.y, acc1[3][1]);
            FFMA2(acc1[4][0], A2.x, wd.x, acc1[4][0]);
            FFMA2(acc1[4][1], A2.x, wd.y, acc1[4][1]);
            FFMA2(acc1[5][0], A2.y, wd.x, acc1[5][0]);
            FFMA2(acc1[5][1], A2.y, wd.y, acc1[5][1]);
            FFMA2(acc1[6][0], A3.x, wd.x, acc1[6][0]);
            FFMA2(acc1[6][1], A3.x, wd.y, acc1[6][1]);
            FFMA2(acc1[7][0], A3.y, wd.x, acc1[7][0]);
            FFMA2(acc1[7][1], A3.y, wd.y, acc1[7][1]);
        }
    }
    __syncthreads();   // all x-tile reads done before overwrite

    // write xp into xS[f][t]: per col a contiguous 16-t run = 4 STS.128
    {
#pragma unroll
        for (int c = 0; c < 2; c++) {
            float* row = &xS[(c0 + c) * PCH + tg1 * 16];
            ull2 s0; s0.x = acc1[0][c]; s0.y = acc1[1][c];
            ull2 s1; s1.x = acc1[2][c]; s1.y = acc1[3][c];
            ull2 s2; s2.x = acc1[4][c]; s2.y = acc1[5][c];
            ull2 s3; s3.x = acc1[6][c]; s3.y = acc1[7][c];
            *(ull2*)row        = s0;
            *(ull2*)(row + 4)  = s1;
            *(ull2*)(row + 8)  = s2;
            *(ull2*)(row + 12) = s3;
        }
    }
    __syncthreads();

    // ---- stage 2: DFT gating -- thread = dim d, all 16 bins ----------------
    {
        float xr[TT];
        const float* col = &xS[tid * PCH];
#pragma unroll
        for (int k = 0; k < 8; k++) {
            float4 v = *(const float4*)&col[4 * k];
            xr[4*k] = v.x; xr[4*k+1] = v.y; xr[4*k+2] = v.z; xr[4*k+3] = v.w;
        }

        float amp[16];
        amp[0]  = dft_amp<1>(xr);  amp[1]  = dft_amp<2>(xr);
        amp[2]  = dft_amp<3>(xr);  amp[3]  = dft_amp<4>(xr);
        amp[4]  = dft_amp<5>(xr);  amp[5]  = dft_amp<6>(xr);
        amp[6]  = dft_amp<7>(xr);  amp[7]  = dft_amp<8>(xr);
        amp[8]  = dft_amp<9>(xr);  amp[9]  = dft_amp<10>(xr);
        amp[10] = dft_amp<11>(xr); amp[11] = dft_amp<12>(xr);
        amp[12] = dft_amp<13>(xr); amp[13] = dft_amp<14>(xr);
        amp[14] = dft_amp<15>(xr); amp[15] = dft_amp<16>(xr);

        float acc9[EE];
#pragma unroll
        for (int e = 0; e < EE; e++) acc9[e] = 0.0f;
#pragma unroll
        for (int f = 0; f < 16; f++) {
            const float a = amp[f];
            const float* wrow = &wgS[f * EE];
#pragma unroll
            for (int e = 0; e < EE; e++) acc9[e] = fmaf(a, wrow[e], acc9[e]);
        }

#pragma unroll
        for (int e = 0; e < EE; e++) {
            float v = acc9[e];
            v += __shfl_down_sync(0xffffffffu, v, 16);
            v += __shfl_down_sync(0xffffffffu, v, 8);
            v += __shfl_down_sync(0xffffffffu, v, 4);
            v += __shfl_down_sync(0xffffffffu, v, 2);
            v += __shfl_down_sync(0xffffffffu, v, 1);
            if (lane == 0) shRed[w1 * EE + e] = v;
        }
    }
    __syncthreads();

    if (tid == 0) {
        float w0 = -1e30f, wsec = -1e30f;
        int e0 = 0, e1 = 0;
#pragma unroll
        for (int e = 0; e < EE; e++) {
            float s = shRed[e] + shRed[EE + e] + shRed[2 * EE + e] + shRed[3 * EE + e];
            float v = s * (1.0f / 128.0f);
            if (v > w0)        { wsec = w0; e1 = e0; w0 = v; e0 = e; }
            else if (v > wsec) { wsec = v; e1 = e; }
        }
        float qv  = __expf(wsec - w0);
        float inv = 1.0f / (1.0f + qv);
        shE[0] = e0; shE[1] = e1;
        shG[0] = inv; shG[1] = qv * inv;
    }
    __syncthreads();

    // ---- stage 3: two routed expert GEMMs (thread: 2 cols x 32 t) ----------
    const int gid = w1 >> 1;
    const int cw3 = w1 & 1;
    const int cp3 = cw3 * 32 + lane;
    const int c3  = 2 * cp3;
    const int e   = shE[gid];
    const float gA = shG[0], gB = shG[1];

    u64 acc3[16][2];
    {
        const float* bee = be + e * 128;
        u64 bd0 = dup_f32(__ldg(bee + c3));
        u64 bd1 = dup_f32(__ldg(bee + c3 + 1));
#pragma unroll
        for (int j = 0; j < 16; j++) { acc3[j][0] = bd0; acc3[j][1] = bd1; }

        const ull2* WbD = gWe + e * (DD * 64);
#pragma unroll 4
        for (int d = 0; d < DD; d++) {
            const float* ar = &xS[d * PCH];
            ull2 wd = ldg_w(WbD + d * 64 + cp3);
#pragma unroll
            for (int q = 0; q < 4; q++) {
                ull2 Aa = *(const ull2*)(ar + 8 * q);
                ull2 Ab = *(const ull2*)(ar + 8 * q + 4);
                FFMA2(acc3[4 * q][0],     Aa.x, wd.x, acc3[4 * q][0]);
                FFMA2(acc3[4 * q][1],     Aa.x, wd.y, acc3[4 * q][1]);
                FFMA2(acc3[4 * q + 1][0], Aa.y, wd.x, acc3[4 * q + 1][0]);
                FFMA2(acc3[4 * q + 1][1], Aa.y, wd.y, acc3[4 * q + 1][1]);
                FFMA2(acc3[4 * q + 2][0], Ab.x, wd.x, acc3[4 * q + 2][0]);
                FFMA2(acc3[4 * q + 2][1], Ab.x, wd.y, acc3[4 * q + 2][1]);
                FFMA2(acc3[4 * q + 3][0], Ab.y, wd.x, acc3[4 * q + 3][0]);
                FFMA2(acc3[4 * q + 3][1], Ab.y, wd.y, acc3[4 * q + 3][1]);
            }
        }
    }
    __syncthreads();   // all xp reads done before overwrite

    // reuse shBuf as ybuf[2][32][128]
    float* ybuf = shBuf;
#pragma unroll
    for (int j = 0; j < 16; j++) {
        float l0, h0, l1, h1;
        unpack_f32x2(acc3[j][0], l0, h0);
        unpack_f32x2(acc3[j][1], l1, h1);
        int base = gid * 4096 + (2 * j) * 128 + c3;
        *(float2*)&ybuf[base]       = make_float2(l0, l1);
        *(float2*)&ybuf[base + 128] = make_float2(h0, h1);
    }
    __syncthreads();

    // ---- stage 4: log-sum-exp combine + store ------------------------------
    float* outp = out + (size_t)n * 4096;
#pragma unroll
    for (int k = 0; k < 8; k++) {
        int i = k * 512 + tid * 4;
        float4 ya = *(const float4*)&ybuf[i];
        float4 yb = *(const float4*)&ybuf[4096 + i];
        float r[4];
        const float yav[4] = {ya.x, ya.y, ya.z, ya.w};
        const float ybv[4] = {yb.x, yb.y, yb.z, yb.w};
#pragma unroll
        for (int j = 0; j < 4; j++) {
            float a = yav[j], bb = ybv[j];
            bool  sel = (a >= bb);
            float m   = sel ? a : bb;
            float gm  = sel ? gA : gB;
            float go  = sel ? gB : gA;
            float ex  = exp_neg_fast((sel ? bb : a) - m);
            r[j] = m + __logf(fmaf(go, ex, gm));
        }
        float4 o; o.x = r[0]; o.y = r[1]; o.z = r[2]; o.w = r[3];
        *(float4*)&outp[i] = o;
    }
}

extern "C" void kernel_launch(void* const* d_in, const int* in_sizes, int n_in,
                              void* d_out, int out_size)
{
    const float* x      = (const float*)d_in[0];
    const float* w_fuse = (const float*)d_in[1];
    const float* b_fuse = (const float*)d_in[2];
    const float* w_gate = (const float*)d_in[3];
    const float* We     = (const float*)d_in[4];
    const float* be     = (const float*)d_in[5];
    float* out = (float*)d_out;

    int total = (1 + EE) * DD * 64;
    prep_dup<<<(total + 255) / 256, 256>>>(w_fuse, We);
    moe_fused_kernel<<<NTOK, 128>>>(x, b_fuse, w_gate, be, out);
}

// round 17
// speedup vs baseline: 1.1788x; 1.1788x over previous
#include <cuda_runtime.h>

// ---------------------------------------------------------------------------
// Fused FourierLayer MoE, fixed shapes:
//   B=2, T=32, C=1, H=16, W=16, D=128, E=9, TOP_K=2  ->  N = 512 tokens
// R17 = R11 (best: 54.6us) + cp.async double-buffered weight staging for both
// GEMMs: LDGSTS prefetches 8-d chunks of weights into smem while computing the
// previous chunk; weight consumption is conflict-free LDS.64 instead of an
// exposed ~250-cyc L2 LDG. Same weight bytes as R11 (R16 showed duplication's
// 2x bytes loses). 128 thr/block, occ 4, single wave.
// ---------------------------------------------------------------------------

typedef unsigned long long u64;
typedef unsigned int u32;
struct ull2 { u64 x, y; };

#define TT 32
#define DD 128
#define EE 9
#define NTOK 512
#define PCH 36      // float pitch: 144B rows -> 16B-aligned, conflict-free LDS.128
#define WB  4608    // float index of weight staging region in shBuf
#define SHN 8704    // shBuf floats: 4608 (xS) + 2*2048 (stage-3 double buffer)

#define FFMA2(d, a, b, c) \
    asm("fma.rn.f32x2 %0, %1, %2, %3;" : "=l"(d) : "l"(a), "l"(b), "l"(c))

#define CP16(dst, src) \
    asm volatile("cp.async.cg.shared.global [%0], [%1], 16;" :: "r"(dst), "l"(src) : "memory")
#define CPCOMMIT() asm volatile("cp.async.commit_group;" ::: "memory")
#define CPWAIT1()  asm volatile("cp.async.wait_group 1;" ::: "memory")
#define CPWAIT0()  asm volatile("cp.async.wait_group 0;" ::: "memory")

__device__ __forceinline__ u32 sh_addr(const void* p) {
    u32 a;
    asm("{ .reg .u64 t; cvta.to.shared.u64 t, %1; cvt.u32.u64 %0, t; }"
        : "=r"(a) : "l"(p));
    return a;
}

__device__ __forceinline__ u64 dup_f32(float v) {
    u32 u = __float_as_uint(v);
    u64 r;
    asm("mov.b64 %0, {%1, %1};" : "=l"(r) : "r"(u));
    return r;
}
__device__ __forceinline__ void unpack_f32x2(u64 p, float &lo, float &hi) {
    u32 a, b;
    asm("mov.b64 {%0, %1}, %2;" : "=r"(a), "=r"(b) : "l"(p));
    lo = __uint_as_float(a); hi = __uint_as_float(b);
}

// e^x for x <= 0, FMA-pipe only. |rel err| < ~2e-7.
__device__ __forceinline__ float exp_neg_fast(float x) {
    float z = x * 1.4426950408889634f;
    z = fmaxf(z, -126.0f);
    float fn = rintf(z);
    float f  = z - fn;
    float p  = 1.5403506e-4f;
    p = fmaf(p, f, 1.3333558e-3f);
    p = fmaf(p, f, 9.6181291e-3f);
    p = fmaf(p, f, 5.5504109e-2f);
    p = fmaf(p, f, 2.4022651e-1f);
    p = fmaf(p, f, 6.9314718e-1f);
    p = fmaf(p, f, 1.0f);
    return p * __int_as_float(((int)fn + 127) << 23);
}

template<int FB>
__device__ __forceinline__ float dft_amp(const float* __restrict__ xr) {
    static constexpr float COS32[32] = {
         1.0f,           0.98078528040f,  0.92387953251f,  0.83146961230f,
         0.70710678119f, 0.55557023302f,  0.38268343237f,  0.19509032202f,
         0.0f,          -0.19509032202f, -0.38268343237f, -0.55557023302f,
        -0.70710678119f,-0.83146961230f, -0.92387953251f, -0.98078528040f,
        -1.0f,          -0.98078528040f, -0.92387953251f, -0.83146961230f,
        -0.70710678119f,-0.55557023302f, -0.38268343237f, -0.19509032202f,
         0.0f,           0.19509032202f,  0.38268343237f,  0.55557023302f,
         0.70710678119f, 0.83146961230f,  0.92387953251f,  0.98078528040f };
    float re = 0.0f, im = 0.0f;
#pragma unroll
    for (int t = 0; t < 32; t++) {
        const float c = COS32[(FB * t) & 31];
        const float s = COS32[((FB * t) + 24) & 31];
        if (c != 0.0f) re = fmaf(xr[t], c, re);
        if (s != 0.0f) im = fmaf(xr[t], s, im);
    }
    return sqrtf(fmaf(re, re, im * im)) * 0.17677669529663688f;
}

__global__ __launch_bounds__(128, 4)
void moe_fused_kernel(const float* __restrict__ x,
                      const float* __restrict__ w_fuse,
                      const float* __restrict__ b_fuse,
                      const float* __restrict__ w_gate,
                      const float* __restrict__ We,
                      const float* __restrict__ be,
                      float* __restrict__ out)
{
    // shBuf regions: [0,4608) xS[128][36]; [4608,8704) weight double-buffer.
    // After stage 3 the first 8192 floats are reused as ybuf[2][32][128].
    __shared__ __align__(16) float shBuf[SHN];
    __shared__ float wgS[16 * EE];
    __shared__ float shRed[4 * EE];
    __shared__ int   shE[2];
    __shared__ float shG[2];

    float* xS = shBuf;
    const u32 wbA = sh_addr(&shBuf[WB]);

    const int n    = blockIdx.x;
    const int tid  = threadIdx.x;
    const int b    = n >> 8;
    const int hw   = n & 255;
    const int lane = tid & 31;
    const int w1   = tid >> 5;

    // ---- stage 0: tables + x tile load (transpose into xS[d][t]) ----------
    for (int i = tid; i < 16 * EE; i += 128) wgS[i] = w_gate[i];

    {
        const float2* x2 = (const float2*)(x + (((size_t)b * TT) << 15) + ((size_t)hw << 7));
#pragma unroll
        for (int k = 0; k < 16; k++) {
            int idx = k * 128 + tid;
            int t   = idx >> 6;
            int d2  = idx & 63;
            float2 v = __ldg(x2 + (size_t)t * 16384 + d2);
            xS[(2 * d2)     * PCH + t] = v.x;
            xS[(2 * d2 + 1) * PCH + t] = v.y;
        }
    }
    __syncthreads();

    // ---- stage 1: fuse GEMM (thread: 2 cols x 16 t), cp.async weights ------
    const int cw1 = w1 & 1;
    const int tg1 = w1 >> 1;           // 0..1
    const int c0  = cw1 * 64 + 2 * lane;

    u64 acc1[8][2];
    {
        u64 bd0 = dup_f32(__ldg(b_fuse + c0));
        u64 bd1 = dup_f32(__ldg(b_fuse + c0 + 1));
#pragma unroll
        for (int j = 0; j < 8; j++) { acc1[j][0] = bd0; acc1[j][1] = bd1; }

        // chunk = 8 d x 128 floats = 1024 floats; 2 float4 per thread
        auto ld1 = [&](int ch, int bf) {
#pragma unroll
            for (int i = 0; i < 2; i++) {
                int f4  = i * 128 + tid;
                int d8  = f4 >> 5;
                int col = (f4 & 31) * 4;
                CP16(wbA + (u32)(bf * 1024 + d8 * 128 + col) * 4,
                     w_fuse + (ch * 8 + d8) * 128 + col);
            }
            CPCOMMIT();
        };

        ld1(0, 0);
        int bf = 0;
#pragma unroll 1
        for (int ch = 0; ch < 16; ch++) {
            if (ch < 15) { ld1(ch + 1, bf ^ 1); CPWAIT1(); } else { CPWAIT0(); }
            __syncthreads();
#pragma unroll
            for (int dd = 0; dd < 8; dd++) {
                int d = ch * 8 + dd;
                const float* ar = &xS[d * PCH + tg1 * 16];
                ull2 A0 = *(const ull2*)ar;
                ull2 A1 = *(const ull2*)(ar + 4);
                ull2 A2 = *(const ull2*)(ar + 8);
                ull2 A3 = *(const ull2*)(ar + 12);
                float2 wv = *(const float2*)&shBuf[WB + bf * 1024 + dd * 128 + c0];
                u64 w0 = dup_f32(wv.x);
                u64 w1d = dup_f32(wv.y);
                FFMA2(acc1[0][0], A0.x, w0,  acc1[0][0]);
                FFMA2(acc1[0][1], A0.x, w1d, acc1[0][1]);
                FFMA2(acc1[1][0], A0.y, w0,  acc1[1][0]);
                FFMA2(acc1[1][1], A0.y, w1d, acc1[1][1]);
                FFMA2(acc1[2][0], A1.x, w0,  acc1[2][0]);
                FFMA2(acc1[2][1], A1.x, w1d, acc1[2][1]);
                FFMA2(acc1[3][0], A1.y, w0,  acc1[3][0]);
                FFMA2(acc1[3][1], A1.y, w1d, acc1[3][1]);
                FFMA2(acc1[4][0], A2.x, w0,  acc1[4][0]);
                FFMA2(acc1[4][1], A2.x, w1d, acc1[4][1]);
                FFMA2(acc1[5][0], A2.y, w0,  acc1[5][0]);
                FFMA2(acc1[5][1], A2.y, w1d, acc1[5][1]);
                FFMA2(acc1[6][0], A3.x, w0,  acc1[6][0]);
                FFMA2(acc1[6][1], A3.x, w1d, acc1[6][1]);
                FFMA2(acc1[7][0], A3.y, w0,  acc1[7][0]);
                FFMA2(acc1[7][1], A3.y, w1d, acc1[7][1]);
            }
            __syncthreads();
            bf ^= 1;
        }
    }

    // write xp into xS[f][t]: per col a contiguous 16-t run = 4 STS.128
    {
#pragma unroll
        for (int c = 0; c < 2; c++) {
            float* row = &xS[(c0 + c) * PCH + tg1 * 16];
            ull2 s0; s0.x = acc1[0][c]; s0.y = acc1[1][c];
            ull2 s1; s1.x = acc1[2][c]; s1.y = acc1[3][c];
            ull2 s2; s2.x = acc1[4][c]; s2.y = acc1[5][c];
            ull2 s3; s3.x = acc1[6][c]; s3.y = acc1[7][c];
            *(ull2*)row        = s0;
            *(ull2*)(row + 4)  = s1;
            *(ull2*)(row + 8)  = s2;
            *(ull2*)(row + 12) = s3;
        }
    }
    __syncthreads();

    // ---- stage 2: DFT gating -- thread = dim d, all 16 bins ----------------
    {
        float xr[TT];
        const float* col = &xS[tid * PCH];
#pragma unroll
        for (int k = 0; k < 8; k++) {
            float4 v = *(const float4*)&col[4 * k];
            xr[4*k] = v.x; xr[4*k+1] = v.y; xr[4*k+2] = v.z; xr[4*k+3] = v.w;
        }

        float amp[16];
        amp[0]  = dft_amp<1>(xr);  amp[1]  = dft_amp<2>(xr);
        amp[2]  = dft_amp<3>(xr);  amp[3]  = dft_amp<4>(xr);
        amp[4]  = dft_amp<5>(xr);  amp[5]  = dft_amp<6>(xr);
        amp[6]  = dft_amp<7>(xr);  amp[7]  = dft_amp<8>(xr);
        amp[8]  = dft_amp<9>(xr);  amp[9]  = dft_amp<10>(xr);
        amp[10] = dft_amp<11>(xr); amp[11] = dft_amp<12>(xr);
        amp[12] = dft_amp<13>(xr); amp[13] = dft_amp<14>(xr);
        amp[14] = dft_amp<15>(xr); amp[15] = dft_amp<16>(xr);

        float acc9[EE];
#pragma unroll
        for (int e = 0; e < EE; e++) acc9[e] = 0.0f;
#pragma unroll
        for (int f = 0; f < 16; f++) {
            const float a = amp[f];
            const float* wrow = &wgS[f * EE];
#pragma unroll
            for (int e = 0; e < EE; e++) acc9[e] = fmaf(a, wrow[e], acc9[e]);
        }

#pragma unroll
        for (int e = 0; e < EE; e++) {
            float v = acc9[e];
            v += __shfl_down_sync(0xffffffffu, v, 16);
            v += __shfl_down_sync(0xffffffffu, v, 8);
            v += __shfl_down_sync(0xffffffffu, v, 4);
            v += __shfl_down_sync(0xffffffffu, v, 2);
            v += __shfl_down_sync(0xffffffffu, v, 1);
            if (lane == 0) shRed[w1 * EE + e] = v;
        }
    }
    __syncthreads();

    if (tid == 0) {
        float w0 = -1e30f, wsec = -1e30f;
        int e0 = 0, e1 = 0;
#pragma unroll
        for (int e = 0; e < EE; e++) {
            float s = shRed[e] + shRed[EE + e] + shRed[2 * EE + e] + shRed[3 * EE + e];
            float v = s * (1.0f / 128.0f);
            if (v > w0)        { wsec = w0; e1 = e0; w0 = v; e0 = e; }
            else if (v > wsec) { wsec = v; e1 = e; }
        }
        float qv  = __expf(wsec - w0);
        float inv = 1.0f / (1.0f + qv);
        shE[0] = e0; shE[1] = e1;
        shG[0] = inv; shG[1] = qv * inv;
    }
    __syncthreads();

    // ---- stage 3: expert GEMMs (thread: 2 cols x 32 t), cp.async weights ---
    const int gid = w1 >> 1;
    const int cw3 = w1 & 1;
    const int c3  = cw3 * 64 + 2 * lane;
    const float gA = shG[0], gB = shG[1];

    u64 acc3[16][2];
    {
        const float* bee = be + shE[gid] * 128;
        u64 bd0 = dup_f32(__ldg(bee + c3));
        u64 bd1 = dup_f32(__ldg(bee + c3 + 1));
#pragma unroll
        for (int j = 0; j < 16; j++) { acc3[j][0] = bd0; acc3[j][1] = bd1; }

        const float* Wb0 = We + (size_t)shE[0] * (DD * DD);
        const float* Wb1 = We + (size_t)shE[1] * (DD * DD);

        // chunk = 8 d x 256 floats (both experts) = 2048 floats; 4 float4/thread
        auto ld3 = [&](int ch, int bf) {
#pragma unroll
            for (int i = 0; i < 4; i++) {
                int f4  = i * 128 + tid;
                int d8  = f4 >> 6;
                int eI  = (f4 >> 5) & 1;
                int col = (f4 & 31) * 4;
                const float* src = (eI ? Wb1 : Wb0) + (ch * 8 + d8) * 128 + col;
                CP16(wbA + (u32)(bf * 2048 + d8 * 256 + eI * 128 + col) * 4, src);
            }
            CPCOMMIT();
        };

        ld3(0, 0);
        int bf = 0;
#pragma unroll 1
        for (int ch = 0; ch < 16; ch++) {
            if (ch < 15) { ld3(ch + 1, bf ^ 1); CPWAIT1(); } else { CPWAIT0(); }
            __syncthreads();
#pragma unroll
            for (int dd = 0; dd < 8; dd++) {
                int d = ch * 8 + dd;
                const float* ar = &xS[d * PCH];
                float2 wv = *(const float2*)&shBuf[WB + bf * 2048 + dd * 256 + gid * 128 + c3];
                u64 w0 = dup_f32(wv.x);
                u64 w1d = dup_f32(wv.y);
#pragma unroll
                for (int q = 0; q < 4; q++) {
                    ull2 Aa = *(const ull2*)(ar + 8 * q);
                    ull2 Ab = *(const ull2*)(ar + 8 * q + 4);
                    FFMA2(acc3[4 * q][0],     Aa.x, w0,  acc3[4 * q][0]);
                    FFMA2(acc3[4 * q][1],     Aa.x, w1d, acc3[4 * q][1]);
                    FFMA2(acc3[4 * q + 1][0], Aa.y, w0,  acc3[4 * q + 1][0]);
                    FFMA2(acc3[4 * q + 1][1], Aa.y, w1d, acc3[4 * q + 1][1]);
                    FFMA2(acc3[4 * q + 2][0], Ab.x, w0,  acc3[4 * q + 2][0]);
                    FFMA2(acc3[4 * q + 2][1], Ab.x, w1d, acc3[4 * q + 2][1]);
                    FFMA2(acc3[4 * q + 3][0], Ab.y, w0,  acc3[4 * q + 3][0]);
                    FFMA2(acc3[4 * q + 3][1], Ab.y, w1d, acc3[4 * q + 3][1]);
                }
            }
            __syncthreads();
            bf ^= 1;
        }
    }

    // reuse shBuf[0..8192) as ybuf[2][32][128] (xS + weight buffers dead)
    float* ybuf = shBuf;
#pragma unroll
    for (int j = 0; j < 16; j++) {
        float l0, h0, l1, h1;
        unpack_f32x2(acc3[j][0], l0, h0);
        unpack_f32x2(acc3[j][1], l1, h1);
        int base = gid * 4096 + (2 * j) * 128 + c3;
        *(float2*)&ybuf[base]       = make_float2(l0, l1);
        *(float2*)&ybuf[base + 128] = make_float2(h0, h1);
    }
    __syncthreads();

    // ---- stage 4: log-sum-exp combine + store ------------------------------
    float* outp = out + (size_t)n * 4096;
#pragma unroll
    for (int k = 0; k < 8; k++) {
        int i = k * 512 + tid * 4;
        float4 ya = *(const float4*)&ybuf[i];
        float4 yb = *(const float4*)&ybuf[4096 + i];
        float r[4];
        const float yav[4] = {ya.x, ya.y, ya.z, ya.w};
        const float ybv[4] = {yb.x, yb.y, yb.z, yb.w};
#pragma unroll
        for (int j = 0; j < 4; j++) {
            float a = yav[j], bb = ybv[j];
            bool  sel = (a >= bb);
            float m   = sel ? a : bb;
            float gm  = sel ? gA : gB;
            float go  = sel ? gB : gA;
            float ex  = exp_neg_fast((sel ? bb : a) - m);
            r[j] = m + __logf(fmaf(go, ex, gm));
        }
        float4 o; o.x = r[0]; o.y = r[1]; o.z = r[2]; o.w = r[3];
        *(float4*)&outp[i] = o;
    }
}

extern "C" void kernel_launch(void* const* d_in, const int* in_sizes, int n_in,
                              void* d_out, int out_size)
{
    const float* x      = (const float*)d_in[0];
    const float* w_fuse = (const float*)d_in[1];
    const float* b_fuse = (const float*)d_in[2];
    const float* w_gate = (const float*)d_in[3];
    const float* We     = (const float*)d_in[4];
    const float* be     = (const float*)d_in[5];
    float* out = (float*)d_out;

    moe_fused_kernel<<<NTOK, 128>>>(x, w_fuse, b_fuse, w_gate, We, be, out);
}